// round 12
// baseline (speedup 1.0000x reference)
#include <cuda_runtime.h>
#include <math.h>

#define T_DIM 4
#define C_DIM 13
#define H_DIM 361
#define W_DIM 720
#define HW    (H_DIM * W_DIM)        /* 259920  */
#define CHW   (C_DIM * HW)           /* 3378960 */
#define N2    (T_DIM * HW)           /* 1039680 */
#define W4    (W_DIM / 4)            /* 180     */
#define N4    (T_DIM * H_DIM * W4)   /* 259920  */

#define TILE_H   2
#define HBLK     181                  /* ceil(361/2) */
#define NBLK_RES (T_DIM * HBLK)      /* 724 blocks  */
#define ROWS_PER_SRC 18              /* 4U + 4V + 4L + 2Lm + 2Lp + 2S */
#define NROWS    (2 * ROWS_PER_SRC)  /* 36 rows of 720 floats */
#define SMEM_FLOATS (NROWS * W_DIM)  /* 25920 */
#define SMEM_BYTES  (SMEM_FLOATS * 4)/* 103680 */

// Scratch (static device globals: allowed; no runtime allocation)
__device__ float  g_Up[N2];
__device__ float  g_Vp[N2];
__device__ float  g_Ut[N2];
__device__ float  g_Vt[N2];
__device__ float  g_lsp[N2];
__device__ float  g_lst[N2];
__device__ float  g_inv_adx[H_DIM];
__device__ float  g_consts[3];          // inv_dt, inv_2dt, inv_ady
__device__ double g_acc;
__device__ unsigned int g_bcount = 0;   // self-resetting via atomicInc wrap

__device__ __forceinline__ float4 LD4(const float* p) {
    return __ldg((const float4*)p);
}
__device__ __forceinline__ unsigned long long pol_evict_first() {
    unsigned long long pol;
    asm("createpolicy.fractional.L2::evict_first.b64 %0, 1.0;" : "=l"(pol));
    return pol;
}
// Streaming read (evict-first): keep the 216MB u/v stream from polluting L2.
__device__ __forceinline__ float4 LD4_STREAM(const float* p, unsigned long long pol) {
    float4 v;
    asm volatile("ld.global.nc.L2::cache_hint.v4.f32 {%0,%1,%2,%3}, [%4], %5;"
                 : "=f"(v.x), "=f"(v.y), "=f"(v.z), "=f"(v.w)
                 : "l"(p), "l"(pol));
    return v;
}
__device__ __forceinline__ unsigned smem_u32(const void* p) {
    return (unsigned)__cvta_generic_to_shared(p);
}
__device__ __forceinline__ void cp_async16(unsigned dst, const void* src) {
    asm volatile("cp.async.cg.shared.global [%0], [%1], 16;"
                 :: "r"(dst), "l"(src));
}

// ---------------------------------------------------------------------------
// Kernel A (unchanged R7/R11 champion): blockIdx.y selects work:
//   y = 0..3 : channel-weighted reduction of one tensor (13 float4 loads/thr)
//   y = 4    : log(sp) for both sources
// ---------------------------------------------------------------------------
__global__ void __launch_bounds__(256) reduce_k(
    const float* __restrict__ up, const float* __restrict__ vp,
    const float* __restrict__ ut, const float* __restrict__ vt,
    const float* __restrict__ spp, const float* __restrict__ spt,
    const float* __restrict__ lat, const float* __restrict__ lev,
    const float* __restrict__ dxp, const float* __restrict__ dtp,
    const float* __restrict__ dyp)
{
    const int ten = blockIdx.y;

    if (blockIdx.x == 0 && ten == 0) {
        for (int r = threadIdx.x; r < H_DIM; r += 256) {
            // Replicate JAX f32 sequence; accurate cos (pole rows dominate)
            float ang = (lat[r] * (float)M_PI) / 180.0f;
            float cv  = (float)cos((double)ang);
            float mpl = (float)(M_PI * 6371000.0 / 180.0);
            float adx = dxp[0] * (mpl * cv);
            g_inv_adx[r] = (float)(1.0 / (double)adx);
        }
        if (threadIdx.x == 0) {
            float dtv = dtp[0];
            float mpl = (float)(M_PI * 6371000.0 / 180.0);
            float ady = dyp[0] * mpl;
            g_consts[0] = (float)(1.0 / (double)dtv);
            g_consts[1] = (float)(1.0 / (2.0 * (double)dtv));
            g_consts[2] = (float)(1.0 / (double)ady);
            g_acc = 0.0;
        }
    }

    int i = blockIdx.x * 256 + threadIdx.x;
    if (i >= N4) return;
    int w4 = i % W4;
    int hh = (i / W4) % H_DIM;
    int t  = i / (W4 * H_DIM);
    int base2 = t * HW  + hh * W_DIM + 4 * w4;

    if (ten == 4) {
        float4 s = LD4(spp + base2);
        float4 l;
        l.x = logf(s.x); l.y = logf(s.y); l.z = logf(s.z); l.w = logf(s.w);
        *(float4*)(g_lsp + base2) = l;
        s = LD4(spt + base2);
        l.x = logf(s.x); l.y = logf(s.y); l.z = logf(s.z); l.w = logf(s.w);
        *(float4*)(g_lst + base2) = l;
        return;
    }

    const float* __restrict__ src;
    float* dst;
    switch (ten) {
        case 0: src = up; dst = g_Up; break;
        case 1: src = vp; dst = g_Vp; break;
        case 2: src = ut; dst = g_Ut; break;
        default: src = vt; dst = g_Vt; break;
    }

    float dpl[C_DIM];
    {
        dpl[0] = (__ldg(lev + 1) - __ldg(lev + 0)) * 100.0f;
        #pragma unroll
        for (int c = 1; c < C_DIM - 1; ++c)
            dpl[c] = (__ldg(lev + c + 1) - __ldg(lev + c - 1)) * 50.0f;
        dpl[C_DIM-1] = (__ldg(lev + C_DIM - 1) - __ldg(lev + C_DIM - 2)) * 100.0f;
    }

    unsigned long long pFirst = pol_evict_first();
    int base5 = t * CHW + hh * W_DIM + 4 * w4;
    float4 acc = make_float4(0.f, 0.f, 0.f, 0.f);
    #pragma unroll
    for (int c = 0; c < C_DIM; ++c) {
        float4 a = LD4_STREAM(src + base5 + c * HW, pFirst);  // evict-first
        float dp = dpl[c];
        acc.x = fmaf(dp, a.x, acc.x);
        acc.y = fmaf(dp, a.y, acc.y);
        acc.z = fmaf(dp, a.z, acc.z);
        acc.w = fmaf(dp, a.w, acc.w);
    }
    *(float4*)(dst + base2) = acc;
}

// ---------------------------------------------------------------------------
// Kernel B: smem-staged stencil. Each block = (t, 2 output rows). Stages 36
// contiguous rows via cp.async (no dest registers -> ~25 copies in flight per
// thread), then computes the residual from shared memory. Boundary handling
// via row-clamping + scale factor (clamped halo == center makes the centered
// difference collapse to the exact one-sided form).
// ---------------------------------------------------------------------------
__global__ void __launch_bounds__(256) stencil_k(
    const float* __restrict__ spp, const float* __restrict__ spt,
    float* __restrict__ out)
{
    extern __shared__ float sm[];
    __shared__ const float* rowsrc[NROWS];

    const int tid = threadIdx.x;
    const int t   = blockIdx.x / HBLK;
    const int h0  = (blockIdx.x % HBLK) * TILE_H;

    // Build the 36-row source table (rows are fully contiguous in gmem).
    if (tid < NROWS) {
        int s = tid / ROWS_PER_SRC;             // 0 = pred, 1 = target
        int j = tid % ROWS_PER_SRC;
        const float* U  = s ? g_Ut  : g_Up;
        const float* V  = s ? g_Vt  : g_Vp;
        const float* L  = s ? g_lst : g_lsp;
        const float* SP = s ? spt   : spp;
        int tm = (t > 0)          ? t - 1 : t;
        int tp = (t < T_DIM - 1)  ? t + 1 : t;
        const float* p;
        int r;
        if (j < 4)       { r = h0 - 1 + j;        p = U  + t  * HW; }
        else if (j < 8)  { r = h0 - 1 + (j - 4);  p = V  + t  * HW; }
        else if (j < 12) { r = h0 - 1 + (j - 8);  p = L  + t  * HW; }
        else if (j < 14) { r = h0 + (j - 12);     p = L  + tm * HW; }
        else if (j < 16) { r = h0 + (j - 14);     p = L  + tp * HW; }
        else             { r = h0 + (j - 16);     p = SP + t  * HW; }
        if (r < 0) r = 0;
        if (r > H_DIM - 1) r = H_DIM - 1;
        rowsrc[tid] = p + r * W_DIM;
    }
    __syncthreads();

    // Stage: 36 rows x 180 float4 = 6480 copies across 256 threads.
    unsigned smbase = smem_u32(sm);
    for (int idx = tid; idx < NROWS * W4; idx += 256) {
        int r  = idx / W4;
        int c4 = idx - r * W4;
        cp_async16(smbase + (unsigned)(r * W_DIM + c4 * 4) * 4u,
                   rowsrc[r] + c4 * 4);
    }
    asm volatile("cp.async.commit_group;");
    asm volatile("cp.async.wait_group 0;" ::: "memory");
    __syncthreads();

    // Compute from smem.
    const float inv_dt  = g_consts[0];
    const float inv_2dt = g_consts[1];
    const float inv_ady = g_consts[2];
    const float tscale  = (t == 0 || t == T_DIM - 1) ? inv_dt : inv_2dt;

    float val = 0.0f;
    for (int w = tid; w < W_DIM; w += 256) {
        int wl = (w == 0) ? 0 : w - 1;
        int wr = (w == W_DIM - 1) ? W_DIM - 1 : w + 1;
        float wscale = (w == 0 || w == W_DIM - 1) ? 1.0f : 0.5f;

        #pragma unroll
        for (int rr = 0; rr < TILE_H; ++rr) {
            int h = h0 + rr;
            if (h >= H_DIM) break;
            float hscale  = (h == 0 || h == H_DIM - 1) ? 1.0f : 0.5f;
            float inv_adx = g_inv_adx[h];
            int cr = rr + 1;   // tile row of h (tile row 0 = h0-1 clamped)

            float res[2];
            #pragma unroll
            for (int s = 0; s < 2; ++s) {
                const float* b  = sm + s * ROWS_PER_SRC * W_DIM;
                const float* Uc = b + (0 + cr) * W_DIM;
                const float* Vm = b + (4 + cr - 1) * W_DIM;
                const float* Vc = b + (4 + cr) * W_DIM;
                const float* Vp = b + (4 + cr + 1) * W_DIM;
                const float* Lm = b + (8 + cr - 1) * W_DIM;
                const float* Lc = b + (8 + cr) * W_DIM;
                const float* Lp = b + (8 + cr + 1) * W_DIM;
                const float* Tm = b + (12 + rr) * W_DIM;
                const float* Tp = b + (14 + rr) * W_DIM;
                const float* Sp = b + (16 + rr) * W_DIM;

                float dls_dt = (Tp[w] - Tm[w]) * tscale;
                float xterm  = (Uc[wr] - Uc[wl]) + Uc[w] * (Lc[wr] - Lc[wl]);
                float yterm  = (Vp[w]  - Vm[w])  + Vc[w] * (Lp[w]  - Lm[w]);
                float integ  = xterm * (wscale * inv_adx)
                             + yterm * (hscale * inv_ady);
                res[s] = dls_dt + __fdividef(integ, Sp[w]);
            }
            float d = res[0] - res[1];
            val = fmaf(d, d, val);
        }
    }

    // Block + global reduction, fused finalize.
    #pragma unroll
    for (int o = 16; o > 0; o >>= 1)
        val += __shfl_down_sync(0xffffffffu, val, o);

    __shared__ float sw[8];
    __shared__ bool  isLast;
    int lane = tid & 31;
    int wid  = tid >> 5;
    if (lane == 0) sw[wid] = val;
    __syncthreads();
    if (wid == 0) {
        float v = (lane < 8) ? sw[lane] : 0.0f;
        #pragma unroll
        for (int o = 4; o > 0; o >>= 1)
            v += __shfl_down_sync(0xffffffffu, v, o);
        if (lane == 0) {
            atomicAdd(&g_acc, (double)v);
            __threadfence();
            unsigned done = atomicInc(&g_bcount, NBLK_RES - 1);
            isLast = (done == NBLK_RES - 1);   // wraps to 0 -> replay-safe
        }
    }
    __syncthreads();
    if (isLast && tid == 0) {
        out[0] = (float)(g_acc / (double)N2);
    }
}

// ---------------------------------------------------------------------------
extern "C" void kernel_launch(void* const* d_in, const int* in_sizes, int n_in,
                              void* d_out, int out_size)
{
    const float* pu  = (const float*)d_in[0];
    const float* pv  = (const float*)d_in[1];
    const float* psp = (const float*)d_in[2];
    const float* tu  = (const float*)d_in[3];
    const float* tv  = (const float*)d_in[4];
    const float* tsp = (const float*)d_in[5];
    const float* lat = (const float*)d_in[6];
    const float* lev = (const float*)d_in[7];
    const float* dt  = (const float*)d_in[8];
    const float* dx  = (const float*)d_in[9];
    const float* dy  = (const float*)d_in[10];

    cudaFuncSetAttribute(stencil_k,
                         cudaFuncAttributeMaxDynamicSharedMemorySize,
                         SMEM_BYTES);

    dim3 gridA(((N4 + 255) / 256), 5);
    reduce_k<<<gridA, 256>>>(pu, pv, tu, tv, psp, tsp, lat, lev, dx, dt, dy);
    stencil_k<<<NBLK_RES, 256, SMEM_BYTES>>>(psp, tsp, (float*)d_out);
}